// round 14
// baseline (speedup 1.0000x reference)
#include <cuda_runtime.h>
#include <cuda_bf16.h>
#include <cstdint>

// Problem constants (shapes fixed by the dataset)
#define NN 500000
#define EE 4000000
#define GG 16384
#define XD 64
#define ED 16
#define INNER 512
#define DEPTH 4

#define FULLMASK 0xffffffffu

// ---------------- scratch (static device allocations; no cudaMalloc) -------
__device__ float g_x0[(size_t)NN * XD];
__device__ float g_x1[(size_t)NN * XD];
__device__ float g_aggE[(size_t)NN * ED];
__device__ float g_fp[(size_t)GG * INNER];
__device__ int   g_deg[NN];
__device__ int   g_rowptr[NN + 1];
__device__ int   g_cursor[NN];
__device__ int   g_bsum[512];
__device__ int   g_psrc[EE];

// ---------------- helpers ----------------
__device__ __forceinline__ float4 ld4(const float* p) {
    return *reinterpret_cast<const float4*>(p);
}
__device__ __forceinline__ float2 ld2(const float* p) {
    return *reinterpret_cast<const float2*>(p);
}
__device__ __forceinline__ void red_add_v4(float* p, float4 v) {
    asm volatile("red.global.add.v4.f32 [%0], {%1,%2,%3,%4};"
                 :: "l"(p), "f"(v.x), "f"(v.y), "f"(v.z), "f"(v.w) : "memory");
}
__device__ __forceinline__ float to_tf32(float f) {
    uint32_t o;
    asm("cvt.rna.tf32.f32 %0, %1;" : "=r"(o) : "f"(f));
    return __uint_as_float(o);
}

// ============================================================================
// kernelAmma: tf32 mma.sync GEMM (logits = x @ W_out^T + b), fused
// softmax (no-max, clamped) + sorted-batch segment-sum into fp.
// MT=64 rows/block, 256 threads, dynamic smem 103424 B -> 2 CTAs/SM.
// R13: pair-permuted W layout -- within each 8-float k-group, element w8 is
// stored at (w8&3)*2 + (w8>>2), so the two B-fragment regs (tq, tq+4) are
// ADJACENT -> one LDS.64 instead of two LDS.32 (+IMAD each). Row stride 72
// floats makes the LDS.64 pattern bank-conflict-free per 16-lane phase.
// W staging double-buffered through registers as in R12.
// ============================================================================
#define MT 64
#define LSPB 520   // bf16 elems per ls row
#define XP 68      // xs (A tile) row stride
#define XPW 72     // W chunk row stride (floats)
#define WCH (64 * XPW)   // floats per W chunk buffer

__global__ void __launch_bounds__(256, 2)
kernelAmma(const float* __restrict__ x, const float* __restrict__ W,
           const float* __restrict__ bias, const int* __restrict__ batch,
           float* __restrict__ fp, int nNodes)
{
    extern __shared__ char dsm[];
    float* Wc = (float*)dsm;                                   // 2 bufs x 18432 B
    __nv_bfloat16* ls = (__nv_bfloat16*)(dsm + 36864);         // 64*520*2 = 66560
    float* xs = (float*)(dsm + 36864);                         // dead after A-frags
    __shared__ float sbias[INNER];
    __shared__ float ssum[2][MT];
    __shared__ float sscale[MT];
    __shared__ int   sbatch[MT];

    const int tid  = threadIdx.x;
    const int w    = tid >> 5, lane = tid & 31;
    const int gid  = lane >> 2, tq = lane & 3;
    const int base = blockIdx.x * MT;
    const int valid = min(MT, nNodes - base);

    for (int i = tid; i < INNER; i += 256) sbias[i] = bias[i];
    if (tid < MT) sbatch[tid] = (tid < valid) ? batch[base + tid] : -1;

    // --- W staging (pair-permuted): thread slice = 4 float4 per 64-row chunk.
    // idx = tid+256t; row n = idx>>4; kq = idx&15 (16 float4 per row).
    // new[kq*4 .. kq*4+3] = old k { g8*8 + par*2 + {0, 4, 1, 5} } where
    // g8 = kq>>1, par = kq&1  (two LDG.64, one STS.128).
    float4 wreg[4];
    #pragma unroll
    for (int t = 0; t < 4; ++t) {
        int idx = tid + 256 * t;
        int n = idx >> 4, kq = idx & 15;
        const float* src = &W[(size_t)n * XD + (kq >> 1) * 8 + (kq & 1) * 2];
        float2 a = ld2(src);
        float2 b = ld2(src + 4);
        float4 v = make_float4(to_tf32(a.x), to_tf32(b.x),
                               to_tf32(a.y), to_tf32(b.y));
        wreg[t] = v;
    }

    // stage x tile (tf32-rounded): 64 rows x 16 float4
    for (int i = tid; i < MT * 16; i += 256) {
        int r = i >> 4, kq = i & 15;
        float4 v = (r < valid) ? ld4(&x[(size_t)(base + r) * XD + kq * 4])
                               : make_float4(0.f, 0.f, 0.f, 0.f);
        v.x = to_tf32(v.x); v.y = to_tf32(v.y); v.z = to_tf32(v.z); v.w = to_tf32(v.w);
        *(float4*)&xs[r * XP + kq * 4] = v;
    }
    __syncthreads();   // xs published

    const int mt = w & 3, half = w >> 2;
    const int m0 = mt * 16;

    // A fragments (per-warp, reused across all chunks): 8 k-steps x 4 regs
    uint32_t A[8][4];
    {
        const uint32_t* xr = (const uint32_t*)xs;
        #pragma unroll
        for (int ks = 0; ks < 8; ++ks) {
            int c0 = ks * 8 + tq;
            A[ks][0] = xr[(m0 + gid) * XP + c0];
            A[ks][1] = xr[(m0 + gid + 8) * XP + c0];
            A[ks][2] = xr[(m0 + gid) * XP + c0 + 4];
            A[ks][3] = xr[(m0 + gid + 8) * XP + c0 + 4];
        }
    }

    // store chunk 0 to buf 0
    {
        float* wb = Wc;
        #pragma unroll
        for (int t = 0; t < 4; ++t) {
            int idx = tid + 256 * t;
            int n = idx >> 4, kq = idx & 15;
            *(float4*)&wb[n * XPW + kq * 4] = wreg[t];
        }
    }

    float rs0 = 0.f, rs1 = 0.f;   // row sums for rows m0+gid and m0+gid+8

    for (int ch = 0; ch < 8; ++ch) {
        // issue next chunk's LDGs (latency hidden behind this chunk's compute)
        if (ch < 7) {
            #pragma unroll
            for (int t = 0; t < 4; ++t) {
                int idx = tid + 256 * t;
                int n = idx >> 4, kq = idx & 15;
                const float* src = &W[(size_t)((ch + 1) * 64 + n) * XD +
                                      (kq >> 1) * 8 + (kq & 1) * 2];
                float2 a = ld2(src);
                float2 b = ld2(src + 4);
                wreg[t] = make_float4(to_tf32(a.x), to_tf32(b.x),
                                      to_tf32(a.y), to_tf32(b.y));
            }
        }
        __syncthreads();   // buf[ch&1] published (and ch=0: A-frag reads done)

        const uint32_t* wr = (const uint32_t*)(Wc + (ch & 1) * WCH);
        const int cb = ch * 64 + half * 32;

        #pragma unroll
        for (int nt = 0; nt < 4; ++nt) {
            const int nloc = half * 32 + nt * 8 + gid;
            const uint32_t* wrow = wr + nloc * XPW + tq * 2;
            // two independent accumulation chains (even/odd k-steps)
            float e0a = 0.f, e1a = 0.f, e2a = 0.f, e3a = 0.f;
            float o0a = 0.f, o1a = 0.f, o2a = 0.f, o3a = 0.f;
            #pragma unroll
            for (int kk = 0; kk < 4; ++kk) {
                const int ke = kk * 2, ko = kk * 2 + 1;
                // pair-permuted layout: {b(tq), b(tq+4)} adjacent -> LDS.64
                uint2 bve = *(const uint2*)&wrow[ke * 8];
                uint2 bvo = *(const uint2*)&wrow[ko * 8];
                asm volatile(
                    "mma.sync.aligned.m16n8k8.row.col.f32.tf32.tf32.f32 "
                    "{%0,%1,%2,%3}, {%4,%5,%6,%7}, {%8,%9}, {%0,%1,%2,%3};"
                    : "+f"(e0a), "+f"(e1a), "+f"(e2a), "+f"(e3a)
                    : "r"(A[ke][0]), "r"(A[ke][1]), "r"(A[ke][2]), "r"(A[ke][3]),
                      "r"(bve.x), "r"(bve.y));
                asm volatile(
                    "mma.sync.aligned.m16n8k8.row.col.f32.tf32.tf32.f32 "
                    "{%0,%1,%2,%3}, {%4,%5,%6,%7}, {%8,%9}, {%0,%1,%2,%3};"
                    : "+f"(o0a), "+f"(o1a), "+f"(o2a), "+f"(o3a)
                    : "r"(A[ko][0]), "r"(A[ko][1]), "r"(A[ko][2]), "r"(A[ko][3]),
                      "r"(bvo.x), "r"(bvo.y));
            }
            const float d0 = e0a + o0a, d1 = e1a + o1a;
            const float d2 = e2a + o2a, d3 = e3a + o3a;

            // fused epilogue: +bias, exp (clamped), row-sum, bf16 store once
            const int c = cb + nt * 8 + tq * 2;
            float e0 = __expf(fminf(d0 + sbias[c],     85.f));
            float e1 = __expf(fminf(d1 + sbias[c + 1], 85.f));
            float e2 = __expf(fminf(d2 + sbias[c],     85.f));
            float e3 = __expf(fminf(d3 + sbias[c + 1], 85.f));
            rs0 += e0 + e1;
            rs1 += e2 + e3;
            const int r0 = m0 + gid, r1 = r0 + 8;
            *(__nv_bfloat162*)&ls[r0 * LSPB + c] = __floats2bfloat162_rn(e0, e1);
            *(__nv_bfloat162*)&ls[r1 * LSPB + c] = __floats2bfloat162_rn(e2, e3);
        }

        // write next chunk into the alternate buffer
        if (ch < 7) {
            float* wb = Wc + ((ch + 1) & 1) * WCH;
            #pragma unroll
            for (int t = 0; t < 4; ++t) {
                int idx = tid + 256 * t;
                int n = idx >> 4, kq = idx & 15;
                *(float4*)&wb[n * XPW + kq * 4] = wreg[t];
            }
        }
    }

    // reduce row sums across the 4-thread quad
    rs0 += __shfl_xor_sync(FULLMASK, rs0, 1);
    rs0 += __shfl_xor_sync(FULLMASK, rs0, 2);
    rs1 += __shfl_xor_sync(FULLMASK, rs1, 1);
    rs1 += __shfl_xor_sync(FULLMASK, rs1, 2);
    if (tq == 0) {
        ssum[half][m0 + gid]     = rs0;
        ssum[half][m0 + gid + 8] = rs1;
    }
    __syncthreads();
    if (tid < MT) sscale[tid] = 1.f / (ssum[0][tid] + ssum[1][tid]);
    __syncthreads();

    // segment-sum into fp (batch sorted -> run-flush), 2 cols per thread
    #pragma unroll
    for (int cc = 0; cc < 2; ++cc) {
        const int c = tid + cc * 256;
        float acc = 0.f;
        int prev = sbatch[0];
        for (int m = 0; m < valid; ++m) {
            int bb = sbatch[m];
            if (bb != prev) {
                atomicAdd(&fp[(size_t)prev * INNER + c], acc);
                acc = 0.f;
                prev = bb;
            }
            acc += __bfloat162float(ls[m * LSPB + c]) * sscale[m];
        }
        if (valid > 0) atomicAdd(&fp[(size_t)prev * INNER + c], acc);
    }
}

// ============================================================================
// CSR-by-dst build (edge_index constant within a call): count, scan, fill.
// ============================================================================
__global__ void countK(const int* __restrict__ ei, int* __restrict__ deg, int nE) {
    int e = blockIdx.x * 256 + threadIdx.x;
    if (e < nE) atomicAdd(&deg[ei[nE + e]], 1);
}

__global__ void scan1K(const int* __restrict__ deg, int* __restrict__ rowptr,
                       int* __restrict__ bsum, int n)
{
    __shared__ int wsum[8], woff[8];
    const int t = threadIdx.x;
    const int base = blockIdx.x * 2048 + t * 8;
    int v[8], s = 0;
    #pragma unroll
    for (int j = 0; j < 8; ++j) {
        int idx = base + j;
        v[j] = (idx < n) ? deg[idx] : 0;
        s += v[j];
    }
    const int lane = t & 31, wid = t >> 5;
    int sc = s;
    #pragma unroll
    for (int o = 1; o < 32; o <<= 1) {
        int u = __shfl_up_sync(FULLMASK, sc, o);
        if (lane >= o) sc += u;
    }
    if (lane == 31) wsum[wid] = sc;
    __syncthreads();
    if (t == 0) {
        int run = 0;
        #pragma unroll
        for (int i = 0; i < 8; ++i) { woff[i] = run; run += wsum[i]; }
        bsum[blockIdx.x] = run;
    }
    __syncthreads();
    int run = woff[wid] + sc - s;     // exclusive prefix for this thread
    #pragma unroll
    for (int j = 0; j < 8; ++j) {
        int idx = base + j;
        if (idx < n) rowptr[idx] = run;
        run += v[j];
    }
}

__global__ void scan2K(int* __restrict__ bsum, int nb) {
    __shared__ int wsum[8], woff[8];
    const int t = threadIdx.x;
    int v = (t < nb) ? bsum[t] : 0;
    const int lane = t & 31, wid = t >> 5;
    int sc = v;
    #pragma unroll
    for (int o = 1; o < 32; o <<= 1) {
        int u = __shfl_up_sync(FULLMASK, sc, o);
        if (lane >= o) sc += u;
    }
    if (lane == 31) wsum[wid] = sc;
    __syncthreads();
    if (t == 0) {
        int run = 0;
        #pragma unroll
        for (int i = 0; i < 8; ++i) { woff[i] = run; run += wsum[i]; }
    }
    __syncthreads();
    if (t < nb) bsum[t] = woff[wid] + sc - v;
}

__global__ void scan3K(int* __restrict__ rowptr, const int* __restrict__ bsum,
                       int n, int nE) {
    int i = blockIdx.x * 256 + threadIdx.x;
    if (i < n) rowptr[i] += bsum[i >> 11];
    if (i == 0) rowptr[n] = nE;
}

__global__ void fillK(const int* __restrict__ ei, int* __restrict__ cursor,
                      int* __restrict__ psrc, int nE) {
    int e = blockIdx.x * 256 + threadIdx.x;
    if (e < nE) {
        int dst = ei[nE + e];
        int p = atomicAdd(&cursor[dst], 1);
        psrc[p] = ei[e];
    }
}

// ============================================================================
// aggEsc: aggE[dst] += edge_attr[e] direct scatter (once per call).
// ============================================================================
__global__ void aggEsc(const float* __restrict__ ea, const int* __restrict__ ei,
                       float* __restrict__ aggE, int nE)
{
    long long gid = (long long)blockIdx.x * 256 + threadIdx.x;
    int e = (int)(gid >> 2), c = (int)(gid & 3);
    if (e >= nE) return;
    int dst = __ldg(&ei[nE + e]);
    float4 a = ld4(&ea[(size_t)e * ED + c * 4]);
    red_add_v4(&aggE[(size_t)dst * ED + c * 4], a);
}

// ============================================================================
// convK: fused gather + self-loop + linear (4-edge unrolled gather).
// x_new[n] = W_in @ concat(x[n] + sum_{e:dst=n} x[src_e], aggE[n]) + b
// ============================================================================
__device__ __forceinline__ void gather_row(
    const float* __restrict__ xin, const int* __restrict__ psrc,
    int r, int re, int lane, float2& acc)
{
    for (; r + 4 <= re; r += 4) {
        int s0 = psrc[r], s1 = psrc[r + 1], s2 = psrc[r + 2], s3 = psrc[r + 3];
        float2 v0 = ld2(&xin[(size_t)s0 * XD + lane * 2]);
        float2 v1 = ld2(&xin[(size_t)s1 * XD + lane * 2]);
        float2 v2 = ld2(&xin[(size_t)s2 * XD + lane * 2]);
        float2 v3 = ld2(&xin[(size_t)s3 * XD + lane * 2]);
        acc.x += (v0.x + v1.x) + (v2.x + v3.x);
        acc.y += (v0.y + v1.y) + (v2.y + v3.y);
    }
    if (r + 2 <= re) {
        int s0 = psrc[r], s1 = psrc[r + 1];
        float2 v0 = ld2(&xin[(size_t)s0 * XD + lane * 2]);
        float2 v1 = ld2(&xin[(size_t)s1 * XD + lane * 2]);
        acc.x += v0.x + v1.x; acc.y += v0.y + v1.y;
        r += 2;
    }
    if (r < re) {
        float2 v = ld2(&xin[(size_t)psrc[r] * XD + lane * 2]);
        acc.x += v.x; acc.y += v.y;
    }
}

__global__ void __launch_bounds__(256) convK(
    const float* __restrict__ xin, const float* __restrict__ aggE,
    const int* __restrict__ rowptr, const int* __restrict__ psrc,
    const float* __restrict__ Wi, const float* __restrict__ bi,
    float* __restrict__ xout, int nNodes)
{
    __shared__ float Wt2[80 * 64];   // [k][2j]=Wi[j][k], [k][2j+1]=Wi[j+32][k]
    __shared__ float sb[64];
    __shared__ float aggA[8][80];
    __shared__ float aggB[8][80];
    const int tid = threadIdx.x, w = tid >> 5, lane = tid & 31;

    for (int i = tid; i < 80 * 64; i += 256) {
        int k = i >> 6, jj = i & 63;
        int j = (jj >> 1) + (jj & 1) * 32;
        Wt2[i] = Wi[j * 80 + k];
    }
    if (tid < 64) sb[tid] = bi[tid];
    __syncthreads();

    const int nbase = blockIdx.x * 64 + w * 8;
    for (int it = 0; it < 4; ++it) {
        const int na = nbase + it * 2;
        const int nb2 = na + 1;
        if (na >= nNodes) break;            // warp-uniform
        const bool vb = nb2 < nNodes;

        float2 accA = ld2(&xin[(size_t)na * XD + lane * 2]);   // self loop
        gather_row(xin, psrc, rowptr[na], rowptr[na + 1], lane, accA);

        float2 accB = make_float2(0.f, 0.f);
        if (vb) {
            accB = ld2(&xin[(size_t)nb2 * XD + lane * 2]);
            gather_row(xin, psrc, rowptr[nb2], rowptr[nb2 + 1], lane, accB);
        }
        *(float2*)&aggA[w][lane * 2] = accA;
        *(float2*)&aggB[w][lane * 2] = accB;
        if (lane < 16) {
            aggA[w][64 + lane] = aggE[(size_t)na * ED + lane];
            aggB[w][64 + lane] = vb ? aggE[(size_t)nb2 * ED + lane] : 0.f;
        }
        __syncwarp();

        float o0a = sb[lane], o1a = sb[lane + 32];
        float o0b = o0a, o1b = o1a;
        #pragma unroll
        for (int k = 0; k < 80; ++k) {
            float2 wt = *(const float2*)&Wt2[k * 64 + lane * 2];
            float a = aggA[w][k], b = aggB[w][k];
            o0a += wt.x * a; o1a += wt.y * a;
            o0b += wt.x * b; o1b += wt.y * b;
        }
        xout[(size_t)na * XD + lane]      = o0a;
        xout[(size_t)na * XD + lane + 32] = o1a;
        if (vb) {
            xout[(size_t)nb2 * XD + lane]      = o0b;
            xout[(size_t)nb2 * XD + lane + 32] = o1b;
        }
        __syncwarp();
    }
}

// ============================================================================
// finalK: out[g] = sigmoid((fp[g] @ lin1^T + b1) @ lin2^T + b2)
// lin1 staged in 100 KB smem; 128 graphs/block.
// ============================================================================
__global__ void __launch_bounds__(256) finalK(
    const float* __restrict__ fp,
    const float* __restrict__ l1w, const float* __restrict__ l1b,
    const float* __restrict__ l2w, const float* __restrict__ l2b,
    float* __restrict__ out, int nG)
{
    extern __shared__ float sw[];   // 50 * 512 floats
    __shared__ float sl1b[50], sl2w[50];
    const int tid = threadIdx.x, w = tid >> 5, lane = tid & 31;

    for (int i = tid; i < 50 * INNER; i += 256) sw[i] = l1w[i];
    if (tid < 50) { sl1b[tid] = l1b[tid]; sl2w[tid] = l2w[tid]; }
    __syncthreads();

    const int gbase = blockIdx.x * 128;
    for (int it = 0; it < 16; ++it) {
        const int g = gbase + it * 8 + w;
        if (g >= nG) continue;
        float f[16];
        #pragma unroll
        for (int j = 0; j < 16; ++j) f[j] = fp[(size_t)g * INNER + lane + j * 32];
        float o2 = 0.f;
        for (int o = 0; o < 50; ++o) {
            float a = 0.f;
            #pragma unroll
            for (int j = 0; j < 16; ++j) a += f[j] * sw[o * INNER + lane + j * 32];
            a += __shfl_xor_sync(FULLMASK, a, 16);
            a += __shfl_xor_sync(FULLMASK, a, 8);
            a += __shfl_xor_sync(FULLMASK, a, 4);
            a += __shfl_xor_sync(FULLMASK, a, 2);
            a += __shfl_xor_sync(FULLMASK, a, 1);
            if (lane == 0) o2 += (a + sl1b[o]) * sl2w[o];
        }
        if (lane == 0) {
            float z = o2 + l2b[0];
            out[g] = 1.f / (1.f + __expf(-z));
        }
    }
}

// ============================================================================
// Host orchestration (graph-capturable).
// kernelAmma(iter 0) stays in the ncu capture slot (-s 5 -c 1).
// ============================================================================
extern "C" void kernel_launch(void* const* d_in, const int* in_sizes, int n_in,
                              void* d_out, int out_size)
{
    const float* x_in  = (const float*)d_in[0];
    const float* eattr = (const float*)d_in[1];
    const float* Winw  = (const float*)d_in[2];
    const float* Winb  = (const float*)d_in[3];
    const float* Woutw = (const float*)d_in[4];
    const float* Woutb = (const float*)d_in[5];
    const float* l1w   = (const float*)d_in[6];
    const float* l1b   = (const float*)d_in[7];
    const float* l2w   = (const float*)d_in[8];
    const float* l2b   = (const float*)d_in[9];
    const int*   ei    = (const int*)d_in[10];
    const int*   batch = (const int*)d_in[11];

    const int nNodes = in_sizes[0] / XD;
    const int nEdges = in_sizes[1] / ED;
    const int nG     = out_size;

    float *x0, *x1, *aggE, *fp;
    int *deg, *rowptr, *cursor, *bsum, *psrc;
    cudaGetSymbolAddress((void**)&x0,     g_x0);
    cudaGetSymbolAddress((void**)&x1,     g_x1);
    cudaGetSymbolAddress((void**)&aggE,   g_aggE);
    cudaGetSymbolAddress((void**)&fp,     g_fp);
    cudaGetSymbolAddress((void**)&deg,    g_deg);
    cudaGetSymbolAddress((void**)&rowptr, g_rowptr);
    cudaGetSymbolAddress((void**)&cursor, g_cursor);
    cudaGetSymbolAddress((void**)&bsum,   g_bsum);
    cudaGetSymbolAddress((void**)&psrc,   g_psrc);

    const int smemA = 36864 + 66560;      // W bufs + ls = 103424 -> 2 CTAs/SM
    cudaFuncSetAttribute(kernelAmma, cudaFuncAttributeMaxDynamicSharedMemorySize, smemA);
    const int smemF = 50 * INNER * (int)sizeof(float);  // 102400
    cudaFuncSetAttribute(finalK, cudaFuncAttributeMaxDynamicSharedMemorySize, smemF);

    cudaMemsetAsync(fp, 0, (size_t)nG * INNER * sizeof(float));
    cudaMemsetAsync(deg, 0, (size_t)nNodes * sizeof(int));
    cudaMemsetAsync(aggE, 0, (size_t)nNodes * ED * sizeof(float));

    const int gridE  = (nEdges + 255) / 256;
    const int nbk    = (nNodes + 2047) / 2048;
    const int gridA  = (nNodes + MT - 1) / MT;
    const int gridConv = (nNodes + 63) / 64;

    // CSR build interleaved with kernelAmma(0) -- kernelAmma(0) sits in the
    // launch slot the profiler captures.
    countK<<<gridE, 256>>>(ei, deg, nEdges);
    scan1K<<<nbk, 256>>>(deg, rowptr, bsum, nNodes);
    scan2K<<<1, 256>>>(bsum, nbk);
    kernelAmma<<<gridA, 256, smemA>>>(x_in, Woutw, Woutb, batch, fp, nNodes);
    scan3K<<<(nNodes + 255) / 256, 256>>>(rowptr, bsum, nNodes, nEdges);
    cudaMemcpyAsync(cursor, rowptr, (size_t)nNodes * sizeof(int),
                    cudaMemcpyDeviceToDevice);
    fillK<<<gridE, 256>>>(ei, cursor, psrc, nEdges);
    aggEsc<<<(int)(((long long)nEdges * 4 + 255) / 256), 256>>>(eattr, ei, aggE, nEdges);

    const float* cur = x_in;
    float* bufs[2] = { x0, x1 };
    int pb = 0;

    for (int i = 0; i < DEPTH; ++i) {
        float* nxt = bufs[pb];
        convK<<<gridConv, 256>>>(cur, aggE, rowptr, psrc, Winw, Winb, nxt, nNodes);
        cur = nxt;
        pb ^= 1;
        kernelAmma<<<gridA, 256, smemA>>>(cur, Woutw, Woutb, batch, fp, nNodes);
    }

    finalK<<<(nG + 127) / 128, 256, smemF>>>(fp, l1w, l1b, l2w, l2b,
                                             (float*)d_out, nG);
}

// round 15
// speedup vs baseline: 1.0560x; 1.0560x over previous
#include <cuda_runtime.h>
#include <cuda_bf16.h>
#include <cstdint>

// Problem constants (shapes fixed by the dataset)
#define NN 500000
#define EE 4000000
#define GG 16384
#define XD 64
#define ED 16
#define INNER 512
#define DEPTH 4

#define FULLMASK 0xffffffffu

// ---------------- scratch (static device allocations; no cudaMalloc) -------
__device__ float g_x0[(size_t)NN * XD];
__device__ float g_x1[(size_t)NN * XD];
__device__ float g_aggE[(size_t)NN * ED];
__device__ float g_fp[(size_t)GG * INNER];
__device__ int   g_deg[NN];
__device__ int   g_rowptr[NN + 1];
__device__ int   g_cursor[NN];
__device__ int   g_bsum[512];
__device__ int   g_psrc[EE];

// ---------------- helpers ----------------
__device__ __forceinline__ float4 ld4(const float* p) {
    return *reinterpret_cast<const float4*>(p);
}
__device__ __forceinline__ float2 ld2(const float* p) {
    return *reinterpret_cast<const float2*>(p);
}
__device__ __forceinline__ void red_add_v4(float* p, float4 v) {
    asm volatile("red.global.add.v4.f32 [%0], {%1,%2,%3,%4};"
                 :: "l"(p), "f"(v.x), "f"(v.y), "f"(v.z), "f"(v.w) : "memory");
}
__device__ __forceinline__ void red_add_v2(float* p, float a, float b) {
    asm volatile("red.global.add.v2.f32 [%0], {%1,%2};"
                 :: "l"(p), "f"(a), "f"(b) : "memory");
}
__device__ __forceinline__ float to_tf32(float f) {
    uint32_t o;
    asm("cvt.rna.tf32.f32 %0, %1;" : "=r"(o) : "f"(f));
    return __uint_as_float(o);
}

// ============================================================================
// kernelAmma: tf32 mma.sync GEMM (logits = x @ W_out^T + b), fused
// softmax (no-max, clamped) + sorted-batch segment-sum into fp.
// MT=64 rows/block, 256 threads, dynamic smem 101376 B -> 2 CTAs/SM.
// R12 MMA/staging config (measured best: 424us). R15: tail rebuilt --
// run boundaries precomputed via ballot (batch sorted, ~2-3 runs/block),
// column-pair processing (1x LDS.32 per row for 2 cols), red.v2 per run.
// ============================================================================
#define MT 64
#define LSPB 520   // bf16 elems per ls row (pad -> conflict-free epilogue stores)
#define XP 68
#define WCH 4352   // floats per W chunk buffer (64 rows x XP)

__global__ void __launch_bounds__(256, 2)
kernelAmma(const float* __restrict__ x, const float* __restrict__ W,
           const float* __restrict__ bias, const int* __restrict__ batch,
           float* __restrict__ fp, int nNodes)
{
    extern __shared__ char dsm[];
    float* Wc = (float*)dsm;                                   // 2 bufs x 17408 B
    __nv_bfloat16* ls = (__nv_bfloat16*)(dsm + 34816);         // 64*520*2 = 66560
    float* xs = (float*)(dsm + 34816);                         // dead after A-frags
    __shared__ float sbias[INNER];
    __shared__ float ssum[2][MT];
    __shared__ float sscale[MT];
    __shared__ int   sbatch[MT];
    __shared__ int   srun[MT + 2];
    __shared__ int   sWcnt[2];
    __shared__ int   snrun;

    const int tid  = threadIdx.x;
    const int w    = tid >> 5, lane = tid & 31;
    const int gid  = lane >> 2, tq = lane & 3;
    const int base = blockIdx.x * MT;
    const int valid = min(MT, nNodes - base);

    for (int i = tid; i < INNER; i += 256) sbias[i] = bias[i];
    if (tid < MT) sbatch[tid] = (tid < valid) ? batch[base + tid] : -1;

    // per-thread W staging slice: 4 float4 per 64-row chunk
    float4 wreg[4];
    {
        #pragma unroll
        for (int t = 0; t < 4; ++t) {
            int idx = tid + 256 * t;
            int n = idx >> 4, kq = idx & 15;
            float4 v = ld4(&W[(size_t)n * XD + kq * 4]);       // chunk 0
            v.x = to_tf32(v.x); v.y = to_tf32(v.y);
            v.z = to_tf32(v.z); v.w = to_tf32(v.w);
            wreg[t] = v;
        }
    }

    // stage x tile (tf32-rounded): 64 rows x 16 float4
    for (int i = tid; i < MT * 16; i += 256) {
        int r = i >> 4, kq = i & 15;
        float4 v = (r < valid) ? ld4(&x[(size_t)(base + r) * XD + kq * 4])
                               : make_float4(0.f, 0.f, 0.f, 0.f);
        v.x = to_tf32(v.x); v.y = to_tf32(v.y); v.z = to_tf32(v.z); v.w = to_tf32(v.w);
        *(float4*)&xs[r * XP + kq * 4] = v;
    }
    __syncthreads();   // xs, sbatch published

    // ---- run-boundary pass 1 (warps 0,1 cover the 64 rows) ----
    int rflag = 0, rpos = 0;
    if (w < 2) {
        rflag = (tid == 0) || (sbatch[tid] != sbatch[tid - 1]);
        unsigned mm = __ballot_sync(FULLMASK, rflag);
        rpos = __popc(mm & ((1u << lane) - 1));
        if (lane == 31) sWcnt[w] = __popc(mm);
        if (w == 0 && rflag) srun[rpos] = tid;
    }

    const int mt = w & 3, half = w >> 2;
    const int m0 = mt * 16;

    // A fragments (per-warp, reused across all chunks): 8 k-steps x 4 regs
    uint32_t A[8][4];
    {
        const uint32_t* xr = (const uint32_t*)xs;
        #pragma unroll
        for (int ks = 0; ks < 8; ++ks) {
            int c0 = ks * 8 + tq;
            A[ks][0] = xr[(m0 + gid) * XP + c0];
            A[ks][1] = xr[(m0 + gid + 8) * XP + c0];
            A[ks][2] = xr[(m0 + gid) * XP + c0 + 4];
            A[ks][3] = xr[(m0 + gid + 8) * XP + c0 + 4];
        }
    }

    // store chunk 0 to buf 0
    {
        float* wb = Wc;
        #pragma unroll
        for (int t = 0; t < 4; ++t) {
            int idx = tid + 256 * t;
            int n = idx >> 4, kq = idx & 15;
            *(float4*)&wb[n * XP + kq * 4] = wreg[t];
        }
    }
    __syncthreads();   // sWcnt published; A-frag reads done

    // ---- run-boundary pass 2 ----
    if (w == 1 && rflag) srun[sWcnt[0] + rpos] = tid;
    if (tid == 0) {
        int nr = sWcnt[0] + sWcnt[1];
        snrun = nr;
        srun[nr] = MT;   // sentinel
    }

    float rs0 = 0.f, rs1 = 0.f;   // row sums for rows m0+gid and m0+gid+8

    for (int ch = 0; ch < 8; ++ch) {
        // issue next chunk's LDGs (latency hidden behind this chunk's compute)
        if (ch < 7) {
            #pragma unroll
            for (int t = 0; t < 4; ++t) {
                int idx = tid + 256 * t;
                int n = idx >> 4, kq = idx & 15;
                float4 v = ld4(&W[(size_t)((ch + 1) * 64 + n) * XD + kq * 4]);
                v.x = to_tf32(v.x); v.y = to_tf32(v.y);
                v.z = to_tf32(v.z); v.w = to_tf32(v.w);
                wreg[t] = v;
            }
        }
        __syncthreads();   // buf[ch&1] published (also publishes srun/snrun)

        const uint32_t* wr = (const uint32_t*)(Wc + (ch & 1) * WCH);
        const int cb = ch * 64 + half * 32;

        #pragma unroll
        for (int nt = 0; nt < 4; ++nt) {
            const int nloc = half * 32 + nt * 8 + gid;
            // two independent accumulation chains (even/odd k-steps)
            float e0a = 0.f, e1a = 0.f, e2a = 0.f, e3a = 0.f;
            float o0a = 0.f, o1a = 0.f, o2a = 0.f, o3a = 0.f;
            #pragma unroll
            for (int kk = 0; kk < 4; ++kk) {
                const int ke = kk * 2, ko = kk * 2 + 1;
                uint32_t be0 = wr[nloc * XP + ke * 8 + tq];
                uint32_t be1 = wr[nloc * XP + ke * 8 + tq + 4];
                uint32_t bo0 = wr[nloc * XP + ko * 8 + tq];
                uint32_t bo1 = wr[nloc * XP + ko * 8 + tq + 4];
                asm volatile(
                    "mma.sync.aligned.m16n8k8.row.col.f32.tf32.tf32.f32 "
                    "{%0,%1,%2,%3}, {%4,%5,%6,%7}, {%8,%9}, {%0,%1,%2,%3};"
                    : "+f"(e0a), "+f"(e1a), "+f"(e2a), "+f"(e3a)
                    : "r"(A[ke][0]), "r"(A[ke][1]), "r"(A[ke][2]), "r"(A[ke][3]),
                      "r"(be0), "r"(be1));
                asm volatile(
                    "mma.sync.aligned.m16n8k8.row.col.f32.tf32.tf32.f32 "
                    "{%0,%1,%2,%3}, {%4,%5,%6,%7}, {%8,%9}, {%0,%1,%2,%3};"
                    : "+f"(o0a), "+f"(o1a), "+f"(o2a), "+f"(o3a)
                    : "r"(A[ko][0]), "r"(A[ko][1]), "r"(A[ko][2]), "r"(A[ko][3]),
                      "r"(bo0), "r"(bo1));
            }
            const float d0 = e0a + o0a, d1 = e1a + o1a;
            const float d2 = e2a + o2a, d3 = e3a + o3a;

            // fused epilogue: +bias, exp (clamped), row-sum, bf16 store once
            const int c = cb + nt * 8 + tq * 2;
            float e0 = __expf(fminf(d0 + sbias[c],     85.f));
            float e1 = __expf(fminf(d1 + sbias[c + 1], 85.f));
            float e2 = __expf(fminf(d2 + sbias[c],     85.f));
            float e3 = __expf(fminf(d3 + sbias[c + 1], 85.f));
            rs0 += e0 + e1;
            rs1 += e2 + e3;
            const int r0 = m0 + gid, r1 = r0 + 8;
            *(__nv_bfloat162*)&ls[r0 * LSPB + c] = __floats2bfloat162_rn(e0, e1);
            *(__nv_bfloat162*)&ls[r1 * LSPB + c] = __floats2bfloat162_rn(e2, e3);
        }

        // write next chunk into the alternate buffer
        if (ch < 7) {
            float* wb = Wc + ((ch + 1) & 1) * WCH;
            #pragma unroll
            for (int t = 0; t < 4; ++t) {
                int idx = tid + 256 * t;
                int n = idx >> 4, kq = idx & 15;
                *(float4*)&wb[n * XP + kq * 4] = wreg[t];
            }
        }
    }

    // reduce row sums across the 4-thread quad
    rs0 += __shfl_xor_sync(FULLMASK, rs0, 1);
    rs0 += __shfl_xor_sync(FULLMASK, rs0, 2);
    rs1 += __shfl_xor_sync(FULLMASK, rs1, 1);
    rs1 += __shfl_xor_sync(FULLMASK, rs1, 2);
    if (tq == 0) {
        ssum[half][m0 + gid]     = rs0;
        ssum[half][m0 + gid + 8] = rs1;
    }
    __syncthreads();
    if (tid < MT) sscale[tid] = 1.f / (ssum[0][tid] + ssum[1][tid]);
    __syncthreads();

    // ---- tail: per-run segment-sum (check-free inner loop), cols (2t,2t+1) ----
    {
        const uint32_t* lsp = (const uint32_t*)ls;   // row stride LSPB/2 = 260
        const int nr = snrun;
        for (int r = 0; r < nr; ++r) {
            const int ms = srun[r];
            int me = srun[r + 1];
            const int b = sbatch[ms];
            if (b < 0) break;                        // trailing invalid-row run
            if (me > valid) me = valid;
            float a0 = 0.f, a1 = 0.f;
            for (int m = ms; m < me; ++m) {
                uint32_t u = lsp[m * (LSPB / 2) + tid];
                __nv_bfloat162 h = *reinterpret_cast<__nv_bfloat162*>(&u);
                float2 f = __bfloat1622float2(h);
                const float s = sscale[m];
                a0 = fmaf(f.x, s, a0);
                a1 = fmaf(f.y, s, a1);
            }
            red_add_v2(&fp[(size_t)b * INNER + tid * 2], a0, a1);
        }
    }
}

// ============================================================================
// CSR-by-dst build (edge_index constant within a call): count, scan, fill.
// ============================================================================
__global__ void countK(const int* __restrict__ ei, int* __restrict__ deg, int nE) {
    int e = blockIdx.x * 256 + threadIdx.x;
    if (e < nE) atomicAdd(&deg[ei[nE + e]], 1);
}

__global__ void scan1K(const int* __restrict__ deg, int* __restrict__ rowptr,
                       int* __restrict__ bsum, int n)
{
    __shared__ int wsum[8], woff[8];
    const int t = threadIdx.x;
    const int base = blockIdx.x * 2048 + t * 8;
    int v[8], s = 0;
    #pragma unroll
    for (int j = 0; j < 8; ++j) {
        int idx = base + j;
        v[j] = (idx < n) ? deg[idx] : 0;
        s += v[j];
    }
    const int lane = t & 31, wid = t >> 5;
    int sc = s;
    #pragma unroll
    for (int o = 1; o < 32; o <<= 1) {
        int u = __shfl_up_sync(FULLMASK, sc, o);
        if (lane >= o) sc += u;
    }
    if (lane == 31) wsum[wid] = sc;
    __syncthreads();
    if (t == 0) {
        int run = 0;
        #pragma unroll
        for (int i = 0; i < 8; ++i) { woff[i] = run; run += wsum[i]; }
        bsum[blockIdx.x] = run;
    }
    __syncthreads();
    int run = woff[wid] + sc - s;     // exclusive prefix for this thread
    #pragma unroll
    for (int j = 0; j < 8; ++j) {
        int idx = base + j;
        if (idx < n) rowptr[idx] = run;
        run += v[j];
    }
}

__global__ void scan2K(int* __restrict__ bsum, int nb) {
    __shared__ int wsum[8], woff[8];
    const int t = threadIdx.x;
    int v = (t < nb) ? bsum[t] : 0;
    const int lane = t & 31, wid = t >> 5;
    int sc = v;
    #pragma unroll
    for (int o = 1; o < 32; o <<= 1) {
        int u = __shfl_up_sync(FULLMASK, sc, o);
        if (lane >= o) sc += u;
    }
    if (lane == 31) wsum[wid] = sc;
    __syncthreads();
    if (t == 0) {
        int run = 0;
        #pragma unroll
        for (int i = 0; i < 8; ++i) { woff[i] = run; run += wsum[i]; }
    }
    __syncthreads();
    if (t < nb) bsum[t] = woff[wid] + sc - v;
}

__global__ void scan3K(int* __restrict__ rowptr, const int* __restrict__ bsum,
                       int n, int nE) {
    int i = blockIdx.x * 256 + threadIdx.x;
    if (i < n) rowptr[i] += bsum[i >> 11];
    if (i == 0) rowptr[n] = nE;
}

__global__ void fillK(const int* __restrict__ ei, int* __restrict__ cursor,
                      int* __restrict__ psrc, int nE) {
    int e = blockIdx.x * 256 + threadIdx.x;
    if (e < nE) {
        int dst = ei[nE + e];
        int p = atomicAdd(&cursor[dst], 1);
        psrc[p] = ei[e];
    }
}

// ============================================================================
// aggEsc: aggE[dst] += edge_attr[e] direct scatter (once per call).
// ============================================================================
__global__ void aggEsc(const float* __restrict__ ea, const int* __restrict__ ei,
                       float* __restrict__ aggE, int nE)
{
    long long gid = (long long)blockIdx.x * 256 + threadIdx.x;
    int e = (int)(gid >> 2), c = (int)(gid & 3);
    if (e >= nE) return;
    int dst = __ldg(&ei[nE + e]);
    float4 a = ld4(&ea[(size_t)e * ED + c * 4]);
    red_add_v4(&aggE[(size_t)dst * ED + c * 4], a);
}

// ============================================================================
// convK: fused gather + self-loop + linear (4-edge unrolled gather).
// x_new[n] = W_in @ concat(x[n] + sum_{e:dst=n} x[src_e], aggE[n]) + b
// ============================================================================
__device__ __forceinline__ void gather_row(
    const float* __restrict__ xin, const int* __restrict__ psrc,
    int r, int re, int lane, float2& acc)
{
    for (; r + 4 <= re; r += 4) {
        int s0 = psrc[r], s1 = psrc[r + 1], s2 = psrc[r + 2], s3 = psrc[r + 3];
        float2 v0 = ld2(&xin[(size_t)s0 * XD + lane * 2]);
        float2 v1 = ld2(&xin[(size_t)s1 * XD + lane * 2]);
        float2 v2 = ld2(&xin[(size_t)s2 * XD + lane * 2]);
        float2 v3 = ld2(&xin[(size_t)s3 * XD + lane * 2]);
        acc.x += (v0.x + v1.x) + (v2.x + v3.x);
        acc.y += (v0.y + v1.y) + (v2.y + v3.y);
    }
    if (r + 2 <= re) {
        int s0 = psrc[r], s1 = psrc[r + 1];
        float2 v0 = ld2(&xin[(size_t)s0 * XD + lane * 2]);
        float2 v1 = ld2(&xin[(size_t)s1 * XD + lane * 2]);
        acc.x += v0.x + v1.x; acc.y += v0.y + v1.y;
        r += 2;
    }
    if (r < re) {
        float2 v = ld2(&xin[(size_t)psrc[r] * XD + lane * 2]);
        acc.x += v.x; acc.y += v.y;
    }
}

__global__ void __launch_bounds__(256) convK(
    const float* __restrict__ xin, const float* __restrict__ aggE,
    const int* __restrict__ rowptr, const int* __restrict__ psrc,
    const float* __restrict__ Wi, const float* __restrict__ bi,
    float* __restrict__ xout, int nNodes)
{
    __shared__ float Wt2[80 * 64];   // [k][2j]=Wi[j][k], [k][2j+1]=Wi[j+32][k]
    __shared__ float sb[64];
    __shared__ float aggA[8][80];
    __shared__ float aggB[8][80];
    const int tid = threadIdx.x, w = tid >> 5, lane = tid & 31;

    for (int i = tid; i < 80 * 64; i += 256) {
        int k = i >> 6, jj = i & 63;
        int j = (jj >> 1) + (jj & 1) * 32;
        Wt2[i] = Wi[j * 80 + k];
    }
    if (tid < 64) sb[tid] = bi[tid];
    __syncthreads();

    const int nbase = blockIdx.x * 64 + w * 8;
    for (int it = 0; it < 4; ++it) {
        const int na = nbase + it * 2;
        const int nb2 = na + 1;
        if (na >= nNodes) break;            // warp-uniform
        const bool vb = nb2 < nNodes;

        float2 accA = ld2(&xin[(size_t)na * XD + lane * 2]);   // self loop
        gather_row(xin, psrc, rowptr[na], rowptr[na + 1], lane, accA);

        float2 accB = make_float2(0.f, 0.f);
        if (vb) {
            accB = ld2(&xin[(size_t)nb2 * XD + lane * 2]);
            gather_row(xin, psrc, rowptr[nb2], rowptr[nb2 + 1], lane, accB);
        }
        *(float2*)&aggA[w][lane * 2] = accA;
        *(float2*)&aggB[w][lane * 2] = accB;
        if (lane < 16) {
            aggA[w][64 + lane] = aggE[(size_t)na * ED + lane];
            aggB[w][64 + lane] = vb ? aggE[(size_t)nb2 * ED + lane] : 0.f;
        }
        __syncwarp();

        float o0a = sb[lane], o1a = sb[lane + 32];
        float o0b = o0a, o1b = o1a;
        #pragma unroll
        for (int k = 0; k < 80; ++k) {
            float2 wt = *(const float2*)&Wt2[k * 64 + lane * 2];
            float a = aggA[w][k], b = aggB[w][k];
            o0a += wt.x * a; o1a += wt.y * a;
            o0b += wt.x * b; o1b += wt.y * b;
        }
        xout[(size_t)na * XD + lane]      = o0a;
        xout[(size_t)na * XD + lane + 32] = o1a;
        if (vb) {
            xout[(size_t)nb2 * XD + lane]      = o0b;
            xout[(size_t)nb2 * XD + lane + 32] = o1b;
        }
        __syncwarp();
    }
}

// ============================================================================
// finalK: out[g] = sigmoid((fp[g] @ lin1^T + b1) @ lin2^T + b2)
// lin1 staged in 100 KB smem; 128 graphs/block.
// ============================================================================
__global__ void __launch_bounds__(256) finalK(
    const float* __restrict__ fp,
    const float* __restrict__ l1w, const float* __restrict__ l1b,
    const float* __restrict__ l2w, const float* __restrict__ l2b,
    float* __restrict__ out, int nG)
{
    extern __shared__ float sw[];   // 50 * 512 floats
    __shared__ float sl1b[50], sl2w[50];
    const int tid = threadIdx.x, w = tid >> 5, lane = tid & 31;

    for (int i = tid; i < 50 * INNER; i += 256) sw[i] = l1w[i];
    if (tid < 50) { sl1b[tid] = l1b[tid]; sl2w[tid] = l2w[tid]; }
    __syncthreads();

    const int gbase = blockIdx.x * 128;
    for (int it = 0; it < 16; ++it) {
        const int g = gbase + it * 8 + w;
        if (g >= nG) continue;
        float f[16];
        #pragma unroll
        for (int j = 0; j < 16; ++j) f[j] = fp[(size_t)g * INNER + lane + j * 32];
        float o2 = 0.f;
        for (int o = 0; o < 50; ++o) {
            float a = 0.f;
            #pragma unroll
            for (int j = 0; j < 16; ++j) a += f[j] * sw[o * INNER + lane + j * 32];
            a += __shfl_xor_sync(FULLMASK, a, 16);
            a += __shfl_xor_sync(FULLMASK, a, 8);
            a += __shfl_xor_sync(FULLMASK, a, 4);
            a += __shfl_xor_sync(FULLMASK, a, 2);
            a += __shfl_xor_sync(FULLMASK, a, 1);
            if (lane == 0) o2 += (a + sl1b[o]) * sl2w[o];
        }
        if (lane == 0) {
            float z = o2 + l2b[0];
            out[g] = 1.f / (1.f + __expf(-z));
        }
    }
}

// ============================================================================
// Host orchestration (graph-capturable).
// kernelAmma(iter 0) stays in the ncu capture slot (-s 5 -c 1).
// ============================================================================
extern "C" void kernel_launch(void* const* d_in, const int* in_sizes, int n_in,
                              void* d_out, int out_size)
{
    const float* x_in  = (const float*)d_in[0];
    const float* eattr = (const float*)d_in[1];
    const float* Winw  = (const float*)d_in[2];
    const float* Winb  = (const float*)d_in[3];
    const float* Woutw = (const float*)d_in[4];
    const float* Woutb = (const float*)d_in[5];
    const float* l1w   = (const float*)d_in[6];
    const float* l1b   = (const float*)d_in[7];
    const float* l2w   = (const float*)d_in[8];
    const float* l2b   = (const float*)d_in[9];
    const int*   ei    = (const int*)d_in[10];
    const int*   batch = (const int*)d_in[11];

    const int nNodes = in_sizes[0] / XD;
    const int nEdges = in_sizes[1] / ED;
    const int nG     = out_size;

    float *x0, *x1, *aggE, *fp;
    int *deg, *rowptr, *cursor, *bsum, *psrc;
    cudaGetSymbolAddress((void**)&x0,     g_x0);
    cudaGetSymbolAddress((void**)&x1,     g_x1);
    cudaGetSymbolAddress((void**)&aggE,   g_aggE);
    cudaGetSymbolAddress((void**)&fp,     g_fp);
    cudaGetSymbolAddress((void**)&deg,    g_deg);
    cudaGetSymbolAddress((void**)&rowptr, g_rowptr);
    cudaGetSymbolAddress((void**)&cursor, g_cursor);
    cudaGetSymbolAddress((void**)&bsum,   g_bsum);
    cudaGetSymbolAddress((void**)&psrc,   g_psrc);

    const int smemA = 34816 + 66560;      // 101376 -> 2 CTAs/SM
    cudaFuncSetAttribute(kernelAmma, cudaFuncAttributeMaxDynamicSharedMemorySize, smemA);
    const int smemF = 50 * INNER * (int)sizeof(float);  // 102400
    cudaFuncSetAttribute(finalK, cudaFuncAttributeMaxDynamicSharedMemorySize, smemF);

    cudaMemsetAsync(fp, 0, (size_t)nG * INNER * sizeof(float));
    cudaMemsetAsync(deg, 0, (size_t)nNodes * sizeof(int));
    cudaMemsetAsync(aggE, 0, (size_t)nNodes * ED * sizeof(float));

    const int gridE  = (nEdges + 255) / 256;
    const int nbk    = (nNodes + 2047) / 2048;
    const int gridA  = (nNodes + MT - 1) / MT;
    const int gridConv = (nNodes + 63) / 64;

    // CSR build interleaved with kernelAmma(0) -- kernelAmma(0) sits in the
    // launch slot the profiler captures.
    countK<<<gridE, 256>>>(ei, deg, nEdges);
    scan1K<<<nbk, 256>>>(deg, rowptr, bsum, nNodes);
    scan2K<<<1, 256>>>(bsum, nbk);
    kernelAmma<<<gridA, 256, smemA>>>(x_in, Woutw, Woutb, batch, fp, nNodes);
    scan3K<<<(nNodes + 255) / 256, 256>>>(rowptr, bsum, nNodes, nEdges);
    cudaMemcpyAsync(cursor, rowptr, (size_t)nNodes * sizeof(int),
                    cudaMemcpyDeviceToDevice);
    fillK<<<gridE, 256>>>(ei, cursor, psrc, nEdges);
    aggEsc<<<(int)(((long long)nEdges * 4 + 255) / 256), 256>>>(eattr, ei, aggE, nEdges);

    const float* cur = x_in;
    float* bufs[2] = { x0, x1 };
    int pb = 0;

    for (int i = 0; i < DEPTH; ++i) {
        float* nxt = bufs[pb];
        convK<<<gridConv, 256>>>(cur, aggE, rowptr, psrc, Winw, Winb, nxt, nNodes);
        cur = nxt;
        pb ^= 1;
        kernelAmma<<<gridA, 256, smemA>>>(cur, Woutw, Woutb, batch, fp, nNodes);
    }

    finalK<<<(nG + 127) / 128, 256, smemF>>>(fp, l1w, l1b, l2w, l2b,
                                             (float*)d_out, nG);
}